// round 3
// baseline (speedup 1.0000x reference)
#include <cuda_runtime.h>
#include <cstdint>

#define DIM    1024
#define QKV_N  3072
#define MTOT   4096          // B*N
#define SEQ    2048
#define RANK   8
#define LSCALE 2.0f
#define QSCALE 0.125f

// -------- scratch --------
__device__ float g_qkv[MTOT * QKV_N];
__device__ float g_attn[MTOT * DIM];
__device__ float g_t1[MTOT * RANK];
__device__ float g_t2[MTOT * RANK];

// -------- tf32 helpers --------
__device__ __forceinline__ unsigned f2tf(float x) {
    unsigned u; asm("cvt.rna.tf32.f32 %0, %1;" : "=r"(u) : "f"(x)); return u;
}
__device__ __forceinline__ void mma8(float* d, const unsigned* a, unsigned b0, unsigned b1) {
    asm("mma.sync.aligned.m16n8k8.row.col.f32.tf32.tf32.f32 "
        "{%0,%1,%2,%3},{%4,%5,%6,%7},{%8,%9},{%0,%1,%2,%3};"
        : "+f"(d[0]), "+f"(d[1]), "+f"(d[2]), "+f"(d[3])
        : "r"(a[0]), "r"(a[1]), "r"(a[2]), "r"(a[3]), "r"(b0), "r"(b1));
}
__device__ __forceinline__ uint4 pack_tf(float4 v) {
    uint4 u; u.x = f2tf(v.x); u.y = f2tf(v.y); u.z = f2tf(v.z); u.w = f2tf(v.w); return u;
}

// ---------------- LoRA down: t = LSCALE * (X @ A^T), one warp per row ----------------
__global__ void lora_down_kernel(const float* __restrict__ x,
                                 const float* __restrict__ A,
                                 float* __restrict__ t)
{
    int warp = (blockIdx.x * blockDim.x + threadIdx.x) >> 5;
    int lane = threadIdx.x & 31;
    if (warp >= MTOT) return;
    const float4* xr = (const float4*)(x + (size_t)warp * DIM);
    float acc[RANK];
#pragma unroll
    for (int r = 0; r < RANK; r++) acc[r] = 0.f;
#pragma unroll
    for (int k = lane; k < DIM / 4; k += 32) {
        float4 xv = xr[k];
#pragma unroll
        for (int r = 0; r < RANK; r++) {
            float4 av = *(const float4*)&A[r * DIM + 4 * k];
            acc[r] += xv.x * av.x + xv.y * av.y + xv.z * av.z + xv.w * av.w;
        }
    }
#pragma unroll
    for (int r = 0; r < RANK; r++) {
#pragma unroll
        for (int off = 16; off > 0; off >>= 1)
            acc[r] += __shfl_xor_sync(0xffffffffu, acc[r], off);
    }
    if (lane == 0) {
#pragma unroll
        for (int r = 0; r < RANK; r++)
            t[warp * RANK + r] = LSCALE * acc[r];
    }
}

// ---------------- TF32 GEMM, software-pipelined, double-buffered ----------------
// C = A[M,K] @ W[N,K]^T; 128x128 tile, BK=16, 8 warps (2m x 4n), warp tile 64x32
#define BK  16
#define GST 20   // 16 + 4 pad: frag banks 20g+t4 all distinct; store rows distinct mod 8

template<int EPI>   // 1: qkv (q cols *QSCALE), 2: proj (+bias)
__global__ void __launch_bounds__(256, 2) gemm_tc(
    const float* __restrict__ A, const float* __restrict__ W,
    float* __restrict__ C, int M, int N, int K,
    const float* __restrict__ lt, const float* __restrict__ lB,
    const float* __restrict__ bias)
{
    __shared__ unsigned As[2][128 * GST];
    __shared__ unsigned Bs[2][128 * GST];
    const int tid = threadIdx.x, warp = tid >> 5, lane = tid & 31;
    const int g = lane >> 2, t4 = lane & 3;
    const int bm = blockIdx.y * 128, bn = blockIdx.x * 128;
    const int wm = (warp & 1) * 64, wn = (warp >> 1) * 32;

    // load assignment: 2 uint4 per matrix per thread per stage
    const int r0l = tid >> 2,  c0l = (tid & 3) << 2;          // u = 0
    const int r1l = (tid + 256) >> 2, c1l = c0l;              // u = 1

    float acc[4][4][4];
#pragma unroll
    for (int mt = 0; mt < 4; mt++)
#pragma unroll
        for (int nt = 0; nt < 4; nt++)
#pragma unroll
            for (int e = 0; e < 4; e++) acc[mt][nt][e] = 0.f;

    float4 a_st[2], b_st[2];
    // prologue: stage k0 = 0
    a_st[0] = *(const float4*)&A[(size_t)(bm + r0l) * K + c0l];
    a_st[1] = *(const float4*)&A[(size_t)(bm + r1l) * K + c1l];
    b_st[0] = *(const float4*)&W[(size_t)(bn + r0l) * K + c0l];
    b_st[1] = *(const float4*)&W[(size_t)(bn + r1l) * K + c1l];
    *(uint4*)&As[0][r0l * GST + c0l] = pack_tf(a_st[0]);
    *(uint4*)&As[0][r1l * GST + c1l] = pack_tf(a_st[1]);
    *(uint4*)&Bs[0][r0l * GST + c0l] = pack_tf(b_st[0]);
    *(uint4*)&Bs[0][r1l * GST + c1l] = pack_tf(b_st[1]);
    __syncthreads();

    int p = 0;
    for (int k0 = 0; k0 < K; k0 += BK) {
        const bool more = (k0 + BK) < K;
        const int kn = more ? k0 + BK : 0;
        // prefetch next stage into registers (overlaps with compute below)
        a_st[0] = *(const float4*)&A[(size_t)(bm + r0l) * K + kn + c0l];
        a_st[1] = *(const float4*)&A[(size_t)(bm + r1l) * K + kn + c1l];
        b_st[0] = *(const float4*)&W[(size_t)(bn + r0l) * K + kn + c0l];
        b_st[1] = *(const float4*)&W[(size_t)(bn + r1l) * K + kn + c1l];

        const unsigned* Ap = As[p];
        const unsigned* Bp = Bs[p];
#pragma unroll
        for (int ks = 0; ks < 2; ks++) {
            const int kk = ks * 8;
            unsigned af[4][4];
#pragma unroll
            for (int mt = 0; mt < 4; mt++) {
                int rr = (wm + 16 * mt + g) * GST + kk + t4;
                af[mt][0] = Ap[rr];
                af[mt][1] = Ap[rr + 8 * GST];
                af[mt][2] = Ap[rr + 4];
                af[mt][3] = Ap[rr + 8 * GST + 4];
            }
#pragma unroll
            for (int nt = 0; nt < 4; nt++) {
                int bb = (wn + 8 * nt + g) * GST + kk + t4;
                unsigned b0 = Bp[bb], b1 = Bp[bb + 4];
#pragma unroll
                for (int mt = 0; mt < 4; mt++)
                    mma8(acc[mt][nt], af[mt], b0, b1);
            }
        }

        if (more) {
            *(uint4*)&As[p ^ 1][r0l * GST + c0l] = pack_tf(a_st[0]);
            *(uint4*)&As[p ^ 1][r1l * GST + c1l] = pack_tf(a_st[1]);
            *(uint4*)&Bs[p ^ 1][r0l * GST + c0l] = pack_tf(b_st[0]);
            *(uint4*)&Bs[p ^ 1][r1l * GST + c1l] = pack_tf(b_st[1]);
            __syncthreads();
            p ^= 1;
        }
    }

    // epilogue: + lt @ lB^T (+bias) (*QSCALE on q cols)
#pragma unroll
    for (int mt = 0; mt < 4; mt++) {
        const int r0 = bm + wm + 16 * mt + g;
        float lt0[RANK], lt1[RANK];
#pragma unroll
        for (int r = 0; r < RANK; r++) {
            lt0[r] = lt[r0 * RANK + r];
            lt1[r] = lt[(r0 + 8) * RANK + r];
        }
#pragma unroll
        for (int nt = 0; nt < 4; nt++) {
            const int c0 = bn + wn + 8 * nt + 2 * t4;
            float v[4] = {acc[mt][nt][0], acc[mt][nt][1], acc[mt][nt][2], acc[mt][nt][3]};
#pragma unroll
            for (int e = 0; e < 2; e++) {
                const int gc = c0 + e;
                float s0 = 0.f, s1 = 0.f;
#pragma unroll
                for (int r = 0; r < RANK; r++) {
                    float bw = lB[gc * RANK + r];
                    s0 += lt0[r] * bw;
                    s1 += lt1[r] * bw;
                }
                v[e]     += s0;
                v[2 + e] += s1;
                if (EPI == 2) { float bb = bias[gc]; v[e] += bb; v[2 + e] += bb; }
                if (EPI == 1 && gc < DIM) { v[e] *= QSCALE; v[2 + e] *= QSCALE; }
            }
            *(float2*)&C[(size_t)r0 * N + c0]       = make_float2(v[0], v[1]);
            *(float2*)&C[(size_t)(r0 + 8) * N + c0] = make_float2(v[2], v[3]);
        }
    }
}

// ---------------- TF32 flash attention, pipelined K/V double buffer ----------------
#define AST 68   // Ps/Ks stride (64+4)
#define VST 72   // Vs stride (64+8)
#define NKB (SEQ / 64)

__global__ void __launch_bounds__(256, 1) attn_tc(const float* __restrict__ qkv,
                                                  float* __restrict__ aout)
{
    extern __shared__ unsigned smem_u[];
    unsigned* Ps = smem_u;                         // 128*AST (Q staging, then P)
    unsigned* Ks0 = smem_u + 128 * AST;            // 2 stages of 64*AST
    unsigned* Vs0 = Ks0 + 2 * 64 * AST;            // 2 stages of 64*VST

    const int tid = threadIdx.x, warp = tid >> 5, lane = tid & 31;
    const int g = lane >> 2, t4 = lane & 3;
    const int qt = blockIdx.x, h = blockIdx.y, b = blockIdx.z;
    const float* base = qkv + (size_t)b * SEQ * QKV_N;
    const int qrow0 = qt * 128, hoff = h * 64, wr = warp * 16;

    // per-thread K/V staging coordinates: 4 rows x float4
    const int jst = tid >> 4, d4st = (tid & 15) << 2;

    // stage Q (tf32) into Ps
#pragma unroll
    for (int u = 0; u < 8; u++) {
        int f = tid + 256 * u;
        int r = f >> 4, d4 = (f & 15) << 2;
        float4 q4 = *(const float4*)&base[(size_t)(qrow0 + r) * QKV_N + hoff + d4];
        *(uint4*)&Ps[r * AST + d4] = pack_tf(q4);
    }

    // prefetch K/V block 0 into registers
    float4 kst[4], vst[4];
#pragma unroll
    for (int u = 0; u < 4; u++) {
        const float* rp = &base[(size_t)(jst + 16 * u) * QKV_N + hoff + d4st];
        kst[u] = *(const float4*)&rp[DIM];
        vst[u] = *(const float4*)&rp[2 * DIM];
    }
    __syncthreads();

    // Q fragments, register resident
    unsigned qf[8][4];
    {
        int r0 = (wr + g) * AST, r1 = (wr + 8 + g) * AST;
#pragma unroll
        for (int kk = 0; kk < 8; kk++) {
            int c = kk * 8 + t4;
            qf[kk][0] = Ps[r0 + c];
            qf[kk][1] = Ps[r1 + c];
            qf[kk][2] = Ps[r0 + c + 4];
            qf[kk][3] = Ps[r1 + c + 4];
        }
    }
    // store K/V block 0 into stage 0
#pragma unroll
    for (int u = 0; u < 4; u++) {
        int j = jst + 16 * u;
        *(uint4*)&Ks0[j * AST + d4st] = pack_tf(kst[u]);
        *(uint4*)&Vs0[j * VST + d4st] = pack_tf(vst[u]);
    }
    __syncthreads();

    float o[8][4];
#pragma unroll
    for (int nt = 0; nt < 8; nt++)
#pragma unroll
        for (int e = 0; e < 4; e++) o[nt][e] = 0.f;
    float mrun[2] = {-1e30f, -1e30f}, lrun[2] = {0.f, 0.f};

    int p = 0;
    for (int kb = 0; kb < NKB; kb++) {
        // prefetch next K/V block into registers (wraps at end; values unused)
        const int krn = ((kb + 1) & (NKB - 1)) * 64;
#pragma unroll
        for (int u = 0; u < 4; u++) {
            const float* rp = &base[(size_t)(krn + jst + 16 * u) * QKV_N + hoff + d4st];
            kst[u] = *(const float4*)&rp[DIM];
            vst[u] = *(const float4*)&rp[2 * DIM];
        }

        const unsigned* Ks = Ks0 + p * 64 * AST;
        const unsigned* Vs = Vs0 + p * 64 * VST;

        // S = Q K^T
        float s[8][4];
#pragma unroll
        for (int nt = 0; nt < 8; nt++)
#pragma unroll
            for (int e = 0; e < 4; e++) s[nt][e] = 0.f;
#pragma unroll
        for (int nt = 0; nt < 8; nt++) {
            int bb = (8 * nt + g) * AST + t4;
#pragma unroll
            for (int kk = 0; kk < 8; kk++)
                mma8(s[nt], qf[kk], Ks[bb + kk * 8], Ks[bb + kk * 8 + 4]);
        }

        // online softmax per row-half
#pragma unroll
        for (int hh = 0; hh < 2; hh++) {
            float mx = -1e30f;
#pragma unroll
            for (int nt = 0; nt < 8; nt++)
                mx = fmaxf(mx, fmaxf(s[nt][2 * hh], s[nt][2 * hh + 1]));
            mx = fmaxf(mx, __shfl_xor_sync(0xffffffffu, mx, 1));
            mx = fmaxf(mx, __shfl_xor_sync(0xffffffffu, mx, 2));
            float mn = fmaxf(mrun[hh], mx);
            float alpha = __expf(mrun[hh] - mn);
            float sum = 0.f;
            int prow = (wr + g + 8 * hh) * AST;
#pragma unroll
            for (int nt = 0; nt < 8; nt++) {
                float p0 = __expf(s[nt][2 * hh] - mn);
                float p1 = __expf(s[nt][2 * hh + 1] - mn);
                sum += p0 + p1;
                uint2 pp; pp.x = f2tf(p0); pp.y = f2tf(p1);
                *(uint2*)&Ps[prow + 8 * nt + 2 * t4] = pp;
            }
            sum += __shfl_xor_sync(0xffffffffu, sum, 1);
            sum += __shfl_xor_sync(0xffffffffu, sum, 2);
            lrun[hh] = lrun[hh] * alpha + sum;
            mrun[hh] = mn;
#pragma unroll
            for (int nt = 0; nt < 8; nt++) {
                o[nt][2 * hh]     *= alpha;
                o[nt][2 * hh + 1] *= alpha;
            }
        }

        // store next K/V stage (frees staging regs; other stage, no conflict)
        {
            unsigned* Kn = Ks0 + (p ^ 1) * 64 * AST;
            unsigned* Vn = Vs0 + (p ^ 1) * 64 * VST;
#pragma unroll
            for (int u = 0; u < 4; u++) {
                int j = jst + 16 * u;
                *(uint4*)&Kn[j * AST + d4st] = pack_tf(kst[u]);
                *(uint4*)&Vn[j * VST + d4st] = pack_tf(vst[u]);
            }
        }
        __syncwarp();   // P written by this warp, read cross-lane below

        // O += P V
#pragma unroll
        for (int kk = 0; kk < 8; kk++) {
            unsigned pa[4];
            int r0 = (wr + g) * AST + kk * 8 + t4;
            pa[0] = Ps[r0];
            pa[1] = Ps[r0 + 8 * AST];
            pa[2] = Ps[r0 + 4];
            pa[3] = Ps[r0 + 8 * AST + 4];
            int vb0 = (kk * 8 + t4) * VST + g;
            int vb1 = vb0 + 4 * VST;
#pragma unroll
            for (int nt = 0; nt < 8; nt++)
                mma8(o[nt], pa, Vs[vb0 + 8 * nt], Vs[vb1 + 8 * nt]);
        }

        __syncthreads();   // stage p fully consumed; next iter reads p^1
        p ^= 1;
    }

    // normalize + store
#pragma unroll
    for (int hh = 0; hh < 2; hh++) {
        float inv = 1.f / lrun[hh];
        int row = qrow0 + wr + g + 8 * hh;
        float* op = &aout[((size_t)b * SEQ + row) * DIM + hoff + 2 * t4];
#pragma unroll
        for (int nt = 0; nt < 8; nt++)
            *(float2*)&op[8 * nt] = make_float2(o[nt][2 * hh] * inv,
                                                o[nt][2 * hh + 1] * inv);
    }
}

// ---------------- launch ----------------
extern "C" void kernel_launch(void* const* d_in, const int* in_sizes, int n_in,
                              void* d_out, int out_size)
{
    const float* x      = (const float*)d_in[0];
    const float* qkv_w  = (const float*)d_in[1];
    const float* proj_w = (const float*)d_in[2];
    const float* proj_b = (const float*)d_in[3];
    const float* A1     = (const float*)d_in[4];
    const float* B1     = (const float*)d_in[5];
    const float* A2     = (const float*)d_in[6];
    const float* B2     = (const float*)d_in[7];
    float* out = (float*)d_out;

    float *p_qkv, *p_attn, *p_t1, *p_t2;
    cudaGetSymbolAddress((void**)&p_qkv,  g_qkv);
    cudaGetSymbolAddress((void**)&p_attn, g_attn);
    cudaGetSymbolAddress((void**)&p_t1,   g_t1);
    cudaGetSymbolAddress((void**)&p_t2,   g_t2);

    const int smem_attn = (128 * AST + 2 * 64 * AST + 2 * 64 * VST) * (int)sizeof(unsigned);
    cudaFuncSetAttribute(attn_tc, cudaFuncAttributeMaxDynamicSharedMemorySize, smem_attn);

    // 1) t1 = 2*(x @ A1^T)
    lora_down_kernel<<<MTOT * 32 / 256, 256>>>(x, A1, p_t1);

    // 2) qkv = x @ qkv_w^T + t1 @ B1^T ; q cols scaled
    gemm_tc<1><<<dim3(QKV_N / 128, MTOT / 128), 256>>>(
        x, qkv_w, p_qkv, MTOT, QKV_N, DIM, p_t1, B1, nullptr);

    // 3) flash attention
    attn_tc<<<dim3(SEQ / 128, 16, 2), 256, smem_attn>>>(p_qkv, p_attn);

    // 4) t2 = 2*(attn @ A2^T)
    lora_down_kernel<<<MTOT * 32 / 256, 256>>>(p_attn, A2, p_t2);

    // 5) out = attn @ proj_w^T + proj_b + t2 @ B2^T
    gemm_tc<2><<<dim3(DIM / 128, MTOT / 128), 256>>>(
        p_attn, proj_w, out, MTOT, DIM, DIM, p_t2, B2, proj_b);
}

// round 4
// speedup vs baseline: 1.0836x; 1.0836x over previous
#include <cuda_runtime.h>
#include <cstdint>

#define DIM    1024
#define QKV_N  3072
#define MTOT   4096          // B*N
#define SEQ    2048
#define RANK   8
#define LSCALE 2.0f
#define QSCALE 0.125f

// -------- scratch --------
__device__ float g_qkv[MTOT * QKV_N];
__device__ float g_attn[MTOT * DIM];
__device__ float g_t1[MTOT * RANK];
__device__ float g_t2[MTOT * RANK];
__device__ float g_xr[MTOT * DIM];      // tf32-rounded x
__device__ float g_qw[QKV_N * DIM];     // tf32-rounded qkv_w
__device__ float g_pw[DIM * DIM];       // tf32-rounded proj_w

// -------- tf32 / async helpers --------
__device__ __forceinline__ unsigned f2tf(float x) {
    unsigned u; asm("cvt.rna.tf32.f32 %0, %1;" : "=r"(u) : "f"(x)); return u;
}
__device__ __forceinline__ void mma8(float* d, const unsigned* a, unsigned b0, unsigned b1) {
    asm("mma.sync.aligned.m16n8k8.row.col.f32.tf32.tf32.f32 "
        "{%0,%1,%2,%3},{%4,%5,%6,%7},{%8,%9},{%0,%1,%2,%3};"
        : "+f"(d[0]), "+f"(d[1]), "+f"(d[2]), "+f"(d[3])
        : "r"(a[0]), "r"(a[1]), "r"(a[2]), "r"(a[3]), "r"(b0), "r"(b1));
}
__device__ __forceinline__ uint4 pack_tf(float4 v) {
    uint4 u; u.x = f2tf(v.x); u.y = f2tf(v.y); u.z = f2tf(v.z); u.w = f2tf(v.w); return u;
}
__device__ __forceinline__ void cpa16(void* s, const void* g) {
    unsigned sa = (unsigned)__cvta_generic_to_shared(s);
    asm volatile("cp.async.cg.shared.global [%0], [%1], 16;"
                 :: "r"(sa), "l"(__cvta_generic_to_global(g)) : "memory");
}
#define CP_COMMIT() asm volatile("cp.async.commit_group;" ::: "memory")
#define CP_WAIT(n)  asm volatile("cp.async.wait_group %0;" :: "n"(n) : "memory")

// ---------------- prep: tf32-round a buffer (float4 grid-stride) ----------------
__global__ void round_tf32_kernel(const float* __restrict__ src,
                                  float* __restrict__ dst, int n4)
{
    int i = blockIdx.x * blockDim.x + threadIdx.x;
    int stride = gridDim.x * blockDim.x;
    for (; i < n4; i += stride) {
        uint4 u = pack_tf(((const float4*)src)[i]);
        ((float4*)dst)[i] = *(float4*)&u;
    }
}

// ---------------- LoRA down: t = LSCALE * (X @ A^T), one warp per row ----------------
__global__ void lora_down_kernel(const float* __restrict__ x,
                                 const float* __restrict__ A,
                                 float* __restrict__ t)
{
    int warp = (blockIdx.x * blockDim.x + threadIdx.x) >> 5;
    int lane = threadIdx.x & 31;
    if (warp >= MTOT) return;
    const float4* xr = (const float4*)(x + (size_t)warp * DIM);
    float acc[RANK];
#pragma unroll
    for (int r = 0; r < RANK; r++) acc[r] = 0.f;
#pragma unroll
    for (int k = lane; k < DIM / 4; k += 32) {
        float4 xv = xr[k];
#pragma unroll
        for (int r = 0; r < RANK; r++) {
            float4 av = *(const float4*)&A[r * DIM + 4 * k];
            acc[r] += xv.x * av.x + xv.y * av.y + xv.z * av.z + xv.w * av.w;
        }
    }
#pragma unroll
    for (int r = 0; r < RANK; r++) {
#pragma unroll
        for (int off = 16; off > 0; off >>= 1)
            acc[r] += __shfl_xor_sync(0xffffffffu, acc[r], off);
    }
    if (lane == 0) {
#pragma unroll
        for (int r = 0; r < RANK; r++)
            t[warp * RANK + r] = LSCALE * acc[r];
    }
}

// ---------------- TF32 GEMM, cp.async 3-stage pipeline ----------------
// C = A[M,K] @ W[N,K]^T; inputs pre-rounded tf32. 128x128 tile, BK=32,
// 8 warps (2m x 4n), warp tile 64x32, mma m16n8k8. One sync per k-iter.
#define BK   32
#define GST  36      // 32 + 4 pad
#define NSTG 3
#define GSTAGE_U (2 * 128 * GST)   // unsigned per stage (A then B)

template<int EPI>   // 1: qkv (q cols *QSCALE, round all outputs), 2: proj (+bias, raw fp32)
__global__ void __launch_bounds__(256, 2) gemm_tc(
    const float* __restrict__ A, const float* __restrict__ W,
    float* __restrict__ C, int M, int N, int K,
    const float* __restrict__ lt, const float* __restrict__ lB,
    const float* __restrict__ bias)
{
    extern __shared__ unsigned smg[];
    const int tid = threadIdx.x, warp = tid >> 5, lane = tid & 31;
    const int g = lane >> 2, t4 = lane & 3;
    const int bm = blockIdx.y * 128, bn = blockIdx.x * 128;
    const int wm = (warp & 1) * 64, wn = (warp >> 1) * 32;
    const int niter = K / BK;

    float acc[4][4][4];
#pragma unroll
    for (int mt = 0; mt < 4; mt++)
#pragma unroll
        for (int nt = 0; nt < 4; nt++)
#pragma unroll
            for (int e = 0; e < 4; e++) acc[mt][nt][e] = 0.f;

    // issue one stage: 128x32 floats per matrix = 4 float4 per thread per matrix
    auto issue = [&](int it, int stg) {
        unsigned* As = smg + stg * GSTAGE_U;
        unsigned* Bs = As + 128 * GST;
        const int k0 = it * BK;
#pragma unroll
        for (int u = 0; u < 4; u++) {
            int f = tid + 256 * u;
            int r = f >> 3, c4 = (f & 7) << 2;
            cpa16(&As[r * GST + c4], &A[(size_t)(bm + r) * K + k0 + c4]);
            cpa16(&Bs[r * GST + c4], &W[(size_t)(bn + r) * K + k0 + c4]);
        }
    };

    issue(0, 0); CP_COMMIT();
    issue(1, 1); CP_COMMIT();

    for (int it = 0; it < niter; it++) {
        CP_WAIT(1);
        __syncthreads();
        if (it + 2 < niter) issue(it + 2, (it + 2) % NSTG);
        CP_COMMIT();

        const unsigned* Ap = smg + (it % NSTG) * GSTAGE_U;
        const unsigned* Bp = Ap + 128 * GST;
#pragma unroll
        for (int ks = 0; ks < 4; ks++) {
            const int kk = ks * 8;
            unsigned af[4][4];
#pragma unroll
            for (int mt = 0; mt < 4; mt++) {
                int rr = (wm + 16 * mt + g) * GST + kk + t4;
                af[mt][0] = Ap[rr];
                af[mt][1] = Ap[rr + 8 * GST];
                af[mt][2] = Ap[rr + 4];
                af[mt][3] = Ap[rr + 8 * GST + 4];
            }
#pragma unroll
            for (int nt = 0; nt < 4; nt++) {
                int bb = (wn + 8 * nt + g) * GST + kk + t4;
                unsigned b0 = Bp[bb], b1 = Bp[bb + 4];
#pragma unroll
                for (int mt = 0; mt < 4; mt++)
                    mma8(acc[mt][nt], af[mt], b0, b1);
            }
        }
    }

    // epilogue: + lt @ lB^T (+bias) (*QSCALE on q cols) (round for EPI==1)
#pragma unroll
    for (int mt = 0; mt < 4; mt++) {
        const int r0 = bm + wm + 16 * mt + g;
        float lt0[RANK], lt1[RANK];
#pragma unroll
        for (int r = 0; r < RANK; r++) {
            lt0[r] = lt[r0 * RANK + r];
            lt1[r] = lt[(r0 + 8) * RANK + r];
        }
#pragma unroll
        for (int nt = 0; nt < 4; nt++) {
            const int c0 = bn + wn + 8 * nt + 2 * t4;
            float v[4] = {acc[mt][nt][0], acc[mt][nt][1], acc[mt][nt][2], acc[mt][nt][3]};
#pragma unroll
            for (int e = 0; e < 2; e++) {
                const int gc = c0 + e;
                float s0 = 0.f, s1 = 0.f;
#pragma unroll
                for (int r = 0; r < RANK; r++) {
                    float bw = lB[gc * RANK + r];
                    s0 += lt0[r] * bw;
                    s1 += lt1[r] * bw;
                }
                v[e]     += s0;
                v[2 + e] += s1;
                if (EPI == 2) { float bb = bias[gc]; v[e] += bb; v[2 + e] += bb; }
                if (EPI == 1 && gc < DIM) { v[e] *= QSCALE; v[2 + e] *= QSCALE; }
                if (EPI == 1) {
                    v[e]     = __uint_as_float(f2tf(v[e]));
                    v[2 + e] = __uint_as_float(f2tf(v[2 + e]));
                }
            }
            *(float2*)&C[(size_t)r0 * N + c0]       = make_float2(v[0], v[1]);
            *(float2*)&C[(size_t)(r0 + 8) * N + c0] = make_float2(v[2], v[3]);
        }
    }
}

// ---------------- TF32 flash attention, cp.async K/V double buffer ----------------
// qkv is tf32-pre-rounded by the gemm epilogue -> cp.async straight into smem.
#define AST 68   // Ps/Ks stride (64+4)
#define VST 72   // Vs stride (64+8)
#define NKB (SEQ / 64)

__global__ void __launch_bounds__(256, 1) attn_tc(const float* __restrict__ qkv,
                                                  float* __restrict__ aout)
{
    extern __shared__ unsigned smem_u[];
    unsigned* Ps  = smem_u;                    // 128*AST (Q staging, then P)
    unsigned* Ks0 = smem_u + 128 * AST;        // 2 stages of 64*AST
    unsigned* Vs0 = Ks0 + 2 * 64 * AST;        // 2 stages of 64*VST

    const int tid = threadIdx.x, warp = tid >> 5, lane = tid & 31;
    const int g = lane >> 2, t4 = lane & 3;
    const int qt = blockIdx.x, h = blockIdx.y, b = blockIdx.z;
    const float* base = qkv + (size_t)b * SEQ * QKV_N;
    const int qrow0 = qt * 128, hoff = h * 64, wr = warp * 16;

    auto issue_kv = [&](int kb, int stg) {
        unsigned* Ks = Ks0 + stg * 64 * AST;
        unsigned* Vs = Vs0 + stg * 64 * VST;
        const int kr0 = kb * 64;
#pragma unroll
        for (int u = 0; u < 4; u++) {
            int f = tid + 256 * u;
            int j = f >> 4, d4 = (f & 15) << 2;
            const float* rp = &base[(size_t)(kr0 + j) * QKV_N + hoff + d4];
            cpa16(&Ks[j * AST + d4], rp + DIM);
            cpa16(&Vs[j * VST + d4], rp + 2 * DIM);
        }
    };

    // stage Q + KV block 0 (one group)
#pragma unroll
    for (int u = 0; u < 8; u++) {
        int f = tid + 256 * u;
        int r = f >> 4, d4 = (f & 15) << 2;
        cpa16(&Ps[r * AST + d4], &base[(size_t)(qrow0 + r) * QKV_N + hoff + d4]);
    }
    issue_kv(0, 0);
    CP_COMMIT();
    CP_WAIT(0);
    __syncthreads();

    // Q fragments, register resident
    unsigned qf[8][4];
    {
        int r0 = (wr + g) * AST, r1 = (wr + 8 + g) * AST;
#pragma unroll
        for (int kk = 0; kk < 8; kk++) {
            int c = kk * 8 + t4;
            qf[kk][0] = Ps[r0 + c];
            qf[kk][1] = Ps[r1 + c];
            qf[kk][2] = Ps[r0 + c + 4];
            qf[kk][3] = Ps[r1 + c + 4];
        }
    }
    __syncthreads();   // everyone done reading Q from Ps before P overwrites it

    float o[8][4];
#pragma unroll
    for (int nt = 0; nt < 8; nt++)
#pragma unroll
        for (int e = 0; e < 4; e++) o[nt][e] = 0.f;
    float mrun[2] = {-1e30f, -1e30f}, lrun[2] = {0.f, 0.f};

    int p = 0;
    for (int kb = 0; kb < NKB; kb++) {
        // prefetch next K/V block via DMA (overlaps all compute below)
        if (kb + 1 < NKB) issue_kv(kb + 1, p ^ 1);
        CP_COMMIT();
        CP_WAIT(1);        // stage p complete (issued last iter / prologue)
        __syncthreads();

        const unsigned* Ks = Ks0 + p * 64 * AST;
        const unsigned* Vs = Vs0 + p * 64 * VST;

        // S = Q K^T
        float s[8][4];
#pragma unroll
        for (int nt = 0; nt < 8; nt++)
#pragma unroll
            for (int e = 0; e < 4; e++) s[nt][e] = 0.f;
#pragma unroll
        for (int nt = 0; nt < 8; nt++) {
            int bb = (8 * nt + g) * AST + t4;
#pragma unroll
            for (int kk = 0; kk < 8; kk++)
                mma8(s[nt], qf[kk], Ks[bb + kk * 8], Ks[bb + kk * 8 + 4]);
        }

        // online softmax per row-half
#pragma unroll
        for (int hh = 0; hh < 2; hh++) {
            float mx = -1e30f;
#pragma unroll
            for (int nt = 0; nt < 8; nt++)
                mx = fmaxf(mx, fmaxf(s[nt][2 * hh], s[nt][2 * hh + 1]));
            mx = fmaxf(mx, __shfl_xor_sync(0xffffffffu, mx, 1));
            mx = fmaxf(mx, __shfl_xor_sync(0xffffffffu, mx, 2));
            float mn = fmaxf(mrun[hh], mx);
            float alpha = __expf(mrun[hh] - mn);
            float sum = 0.f;
            int prow = (wr + g + 8 * hh) * AST;
#pragma unroll
            for (int nt = 0; nt < 8; nt++) {
                float p0 = __expf(s[nt][2 * hh] - mn);
                float p1 = __expf(s[nt][2 * hh + 1] - mn);
                sum += p0 + p1;
                uint2 pp; pp.x = f2tf(p0); pp.y = f2tf(p1);
                *(uint2*)&Ps[prow + 8 * nt + 2 * t4] = pp;
            }
            sum += __shfl_xor_sync(0xffffffffu, sum, 1);
            sum += __shfl_xor_sync(0xffffffffu, sum, 2);
            lrun[hh] = lrun[hh] * alpha + sum;
            mrun[hh] = mn;
#pragma unroll
            for (int nt = 0; nt < 8; nt++) {
                o[nt][2 * hh]     *= alpha;
                o[nt][2 * hh + 1] *= alpha;
            }
        }
        __syncwarp();   // P of this warp's rows written, read cross-lane below

        // O += P V
#pragma unroll
        for (int kk = 0; kk < 8; kk++) {
            unsigned pa[4];
            int r0 = (wr + g) * AST + kk * 8 + t4;
            pa[0] = Ps[r0];
            pa[1] = Ps[r0 + 8 * AST];
            pa[2] = Ps[r0 + 4];
            pa[3] = Ps[r0 + 8 * AST + 4];
            int vb0 = (kk * 8 + t4) * VST + g;
            int vb1 = vb0 + 4 * VST;
#pragma unroll
            for (int nt = 0; nt < 8; nt++)
                mma8(o[nt], pa, Vs[vb0 + 8 * nt], Vs[vb1 + 8 * nt]);
        }

        __syncthreads();   // stage p consumed before next iter's issue overwrites it
        p ^= 1;
    }

    // normalize + store (tf32-rounded: consumed by tf32 proj gemm + tiny lora)
#pragma unroll
    for (int hh = 0; hh < 2; hh++) {
        float inv = 1.f / lrun[hh];
        int row = qrow0 + wr + g + 8 * hh;
        float* op = &aout[((size_t)b * SEQ + row) * DIM + hoff + 2 * t4];
#pragma unroll
        for (int nt = 0; nt < 8; nt++) {
            float2 w;
            w.x = __uint_as_float(f2tf(o[nt][2 * hh] * inv));
            w.y = __uint_as_float(f2tf(o[nt][2 * hh + 1] * inv));
            *(float2*)&op[8 * nt] = w;
        }
    }
}

// ---------------- launch ----------------
extern "C" void kernel_launch(void* const* d_in, const int* in_sizes, int n_in,
                              void* d_out, int out_size)
{
    const float* x      = (const float*)d_in[0];
    const float* qkv_w  = (const float*)d_in[1];
    const float* proj_w = (const float*)d_in[2];
    const float* proj_b = (const float*)d_in[3];
    const float* A1     = (const float*)d_in[4];
    const float* B1     = (const float*)d_in[5];
    const float* A2     = (const float*)d_in[6];
    const float* B2     = (const float*)d_in[7];
    float* out = (float*)d_out;

    float *p_qkv, *p_attn, *p_t1, *p_t2, *p_xr, *p_qw, *p_pw;
    cudaGetSymbolAddress((void**)&p_qkv,  g_qkv);
    cudaGetSymbolAddress((void**)&p_attn, g_attn);
    cudaGetSymbolAddress((void**)&p_t1,   g_t1);
    cudaGetSymbolAddress((void**)&p_t2,   g_t2);
    cudaGetSymbolAddress((void**)&p_xr,   g_xr);
    cudaGetSymbolAddress((void**)&p_qw,   g_qw);
    cudaGetSymbolAddress((void**)&p_pw,   g_pw);

    const int smem_gemm = NSTG * GSTAGE_U * (int)sizeof(unsigned);          // 110592
    const int smem_attn = (128 * AST + 2 * 64 * AST + 2 * 64 * VST) * (int)sizeof(unsigned);
    cudaFuncSetAttribute(gemm_tc<1>, cudaFuncAttributeMaxDynamicSharedMemorySize, smem_gemm);
    cudaFuncSetAttribute(gemm_tc<2>, cudaFuncAttributeMaxDynamicSharedMemorySize, smem_gemm);
    cudaFuncSetAttribute(attn_tc,    cudaFuncAttributeMaxDynamicSharedMemorySize, smem_attn);

    // 0) pre-round GEMM operands to tf32 (idempotent w.r.t. later cvt.rna)
    round_tf32_kernel<<<512, 256>>>(x,      p_xr, MTOT * DIM / 4);
    round_tf32_kernel<<<512, 256>>>(qkv_w,  p_qw, QKV_N * DIM / 4);
    round_tf32_kernel<<<256, 256>>>(proj_w, p_pw, DIM * DIM / 4);

    // 1) t1 = 2*(x @ A1^T)   (uses unrounded x)
    lora_down_kernel<<<MTOT * 32 / 256, 256>>>(x, A1, p_t1);

    // 2) qkv = x @ qkv_w^T + t1 @ B1^T ; q cols scaled; output tf32-rounded
    gemm_tc<1><<<dim3(QKV_N / 128, MTOT / 128), 256, smem_gemm>>>(
        p_xr, p_qw, p_qkv, MTOT, QKV_N, DIM, p_t1, B1, nullptr);

    // 3) flash attention (output tf32-rounded)
    attn_tc<<<dim3(SEQ / 128, 16, 2), 256, smem_attn>>>(p_qkv, p_attn);

    // 4) t2 = 2*(attn @ A2^T)
    lora_down_kernel<<<MTOT * 32 / 256, 256>>>(p_attn, A2, p_t2);

    // 5) out = attn @ proj_w^T + proj_b + t2 @ B2^T  (full fp32 out)
    gemm_tc<2><<<dim3(DIM / 128, MTOT / 128), 256, smem_gemm>>>(
        p_attn, p_pw, out, MTOT, DIM, DIM, p_t2, B2, proj_b);
}